// round 3
// baseline (speedup 1.0000x reference)
#include <cuda_runtime.h>
#include <cstdint>

#define N_NODES 100000
#define N_EDGES 1600000
#define IN_CH   128
#define HIDDEN  64
#define NCLS    40

// ---------------- scratch (device globals; no allocation allowed) ----------
__device__ int   g_is64;
__device__ int   g_deg[N_NODES];
__device__ int   g_off[N_NODES + 1];
__device__ int   g_cur[N_NODES];
__device__ float g_dinv[N_NODES];
__device__ int   g_src[N_EDGES];
__device__ int   g_dst[N_EDGES];
__device__ int2  g_adj[N_EDGES];                     // (src, norm-as-bits), grouped by dst
__device__ float g_hw  [(size_t)N_NODES * HIDDEN];   // X @ W1
__device__ float g_agg1[(size_t)N_NODES * HIDDEN];   // layer1 aggregated (pre-relu)
__device__ float g_h2w [(size_t)N_NODES * NCLS];     // relu(agg1) @ W2

// ---------------- dtype detection ------------------------------------------
// int64 indices (< 2^31) have zero high words at every odd int32 position;
// int32 edge data has random node ids there. OR the first 4096 odd words.
__global__ void detect_kernel(const int* __restrict__ w) {
    __shared__ int acc;
    if (threadIdx.x == 0) acc = 0;
    __syncthreads();
    int v = 0;
    for (int i = threadIdx.x; i < 4096; i += blockDim.x) v |= w[2 * i + 1];
    atomicOr(&acc, v);
    __syncthreads();
    if (threadIdx.x == 0) g_is64 = (acc == 0) ? 1 : 0;
}

// ---------------- prep kernels ----------------------------------------------
__global__ void zero_deg_kernel() {
    int i = blockIdx.x * blockDim.x + threadIdx.x;
    if (i < N_NODES) g_deg[i] = 0;
}

__global__ void deg_kernel(const int* __restrict__ w) {
    int e = blockIdx.x * blockDim.x + threadIdx.x;
    if (e >= N_EDGES) return;
    int s, d;
    if (g_is64) {                       // int64 layout: low words at even offsets
        s = w[2 * e];
        d = w[2 * (N_EDGES + e)];
    } else {                            // int32 layout
        s = w[e];
        d = w[N_EDGES + e];
    }
    // defensive: invalid ids become self-loop-less no-ops instead of faults
    if ((unsigned)s >= N_NODES) s = 0;
    if ((unsigned)d >= N_NODES) d = 0;
    g_src[e] = s;
    g_dst[e] = d;
    atomicAdd(&g_deg[d], 1);
}

__global__ void dinv_kernel() {
    int i = blockIdx.x * blockDim.x + threadIdx.x;
    if (i < N_NODES) g_dinv[i] = rsqrtf((float)(g_deg[i] + 1));  // +1 self loop
}

// single-block exclusive scan of g_deg -> g_off / g_cur
__global__ void scan_kernel() {
    constexpr int T = 1024;
    __shared__ int part[T];
    int t = threadIdx.x;
    int chunk = (N_NODES + T - 1) / T;
    int beg = t * chunk;
    int end = min(beg + chunk, N_NODES);
    int s = 0;
    for (int i = beg; i < end; i++) s += g_deg[i];
    part[t] = s;
    __syncthreads();
    for (int off = 1; off < T; off <<= 1) {
        int v = (t >= off) ? part[t - off] : 0;
        __syncthreads();
        part[t] += v;
        __syncthreads();
    }
    int run = (t > 0) ? part[t - 1] : 0;  // exclusive prefix
    for (int i = beg; i < end; i++) {
        int d = g_deg[i];
        g_off[i] = run;
        g_cur[i] = run;
        run += d;
    }
    if (t == T - 1) g_off[N_NODES] = run;
}

// counting-sort edges by dst into g_adj, norm precomputed
__global__ void fill_kernel() {
    int e = blockIdx.x * blockDim.x + threadIdx.x;
    if (e >= N_EDGES) return;
    int s = g_src[e];
    int d = g_dst[e];
    int pos = atomicAdd(&g_cur[d], 1);
    float nrm = g_dinv[s] * g_dinv[d];
    g_adj[pos] = make_int2(s, __float_as_int(nrm));
}

// ---------------- GEMM: C[M,NDIM] = (relu?)A[M,KDIM] * W[KDIM,NDIM] --------
// 64 rows/block, 4x4 register micro-tile, W fully smem-resident.
template<int KDIM, int NDIM, bool RELU>
__global__ void gemm_kernel(const float* __restrict__ A,
                            const float* __restrict__ W,
                            float* __restrict__ C, int M) {
    constexpr int TX    = NDIM / 4;     // 16 (gemm1) or 10 (gemm2)
    constexpr int NT    = 16 * TX;      // 256 or 160 threads
    constexpr int PITCH = KDIM + 4;
    extern __shared__ float smem[];
    float* sA = smem;                   // [64][PITCH]
    float* sW = smem + 64 * PITCH;      // [KDIM][NDIM]

    const int tid     = threadIdx.x;
    const int rowbase = blockIdx.x * 64;

    for (int v = tid; v < KDIM * NDIM / 4; v += NT)
        ((float4*)sW)[v] = ((const float4*)W)[v];

    constexpr int KC4 = KDIM / 4;
    for (int v = tid; v < 64 * KC4; v += NT) {
        int r  = v / KC4;
        int kc = (v - r * KC4) * 4;
        int row = rowbase + r;
        float4 a = make_float4(0.f, 0.f, 0.f, 0.f);
        if (row < M) a = *(const float4*)(A + (size_t)row * KDIM + kc);
        if (RELU) {
            a.x = fmaxf(a.x, 0.f); a.y = fmaxf(a.y, 0.f);
            a.z = fmaxf(a.z, 0.f); a.w = fmaxf(a.w, 0.f);
        }
        *(float4*)(sA + r * PITCH + kc) = a;
    }
    __syncthreads();

    const int ty = tid / TX, tx = tid - (tid / TX) * TX;
    float acc[4][4];
#pragma unroll
    for (int i = 0; i < 4; i++)
#pragma unroll
        for (int j = 0; j < 4; j++) acc[i][j] = 0.f;

#pragma unroll 4
    for (int k = 0; k < KDIM; k++) {
        float4 b = *(const float4*)(sW + k * NDIM + 4 * tx);
        float a0 = sA[(4 * ty + 0) * PITCH + k];
        float a1 = sA[(4 * ty + 1) * PITCH + k];
        float a2 = sA[(4 * ty + 2) * PITCH + k];
        float a3 = sA[(4 * ty + 3) * PITCH + k];
        acc[0][0] += a0 * b.x; acc[0][1] += a0 * b.y; acc[0][2] += a0 * b.z; acc[0][3] += a0 * b.w;
        acc[1][0] += a1 * b.x; acc[1][1] += a1 * b.y; acc[1][2] += a1 * b.z; acc[1][3] += a1 * b.w;
        acc[2][0] += a2 * b.x; acc[2][1] += a2 * b.y; acc[2][2] += a2 * b.z; acc[2][3] += a2 * b.w;
        acc[3][0] += a3 * b.x; acc[3][1] += a3 * b.y; acc[3][2] += a3 * b.z; acc[3][3] += a3 * b.w;
    }

#pragma unroll
    for (int i = 0; i < 4; i++) {
        int row = rowbase + 4 * ty + i;
        if (row < M)
            *(float4*)(C + (size_t)row * NDIM + 4 * tx) =
                make_float4(acc[i][0], acc[i][1], acc[i][2], acc[i][3]);
    }
}

// ---------------- CSR aggregation: out[i] = b + dinv_i^2*feat[i] + sum norm*feat[src]
// one warp per node; lane owns channels {lane, lane+32}; coalesced row reads.
template<int CH>
__global__ void aggregate_kernel(const float* __restrict__ feat,
                                 const float* __restrict__ bias,
                                 float* __restrict__ out) {
    int warp = (blockIdx.x * blockDim.x + threadIdx.x) >> 5;
    int lane = threadIdx.x & 31;
    if (warp >= N_NODES) return;
    const int node = warp;
    const int beg = g_off[node];
    const int end = g_off[node + 1];

    constexpr int NC = (CH + 31) / 32;
    float acc[NC];
    {
        float dv = g_dinv[node];
        float s  = dv * dv;
        const float* fr = feat + (size_t)node * CH;
#pragma unroll
        for (int c = 0; c < NC; c++) {
            int col = lane + 32 * c;
            acc[c] = (col < CH) ? fmaf(s, fr[col], bias[col]) : 0.f;
        }
    }

    int k = beg;
    for (; k + 1 < end; k += 2) {
        int2 p0 = g_adj[k];
        int2 p1 = g_adj[k + 1];
        const float* f0 = feat + (size_t)p0.x * CH;
        const float* f1 = feat + (size_t)p1.x * CH;
        float n0 = __int_as_float(p0.y);
        float n1 = __int_as_float(p1.y);
#pragma unroll
        for (int c = 0; c < NC; c++) {
            int col = lane + 32 * c;
            if (col < CH) {
                float v0 = f0[col];
                float v1 = f1[col];
                acc[c] = fmaf(n0, v0, acc[c]);
                acc[c] = fmaf(n1, v1, acc[c]);
            }
        }
    }
    if (k < end) {
        int2 p0 = g_adj[k];
        const float* f0 = feat + (size_t)p0.x * CH;
        float n0 = __int_as_float(p0.y);
#pragma unroll
        for (int c = 0; c < NC; c++) {
            int col = lane + 32 * c;
            if (col < CH) acc[c] = fmaf(n0, f0[col], acc[c]);
        }
    }

    float* po = out + (size_t)node * CH;
#pragma unroll
    for (int c = 0; c < NC; c++) {
        int col = lane + 32 * c;
        if (col < CH) po[col] = acc[c];
    }
}

// ---------------- launch ----------------------------------------------------
extern "C" void kernel_launch(void* const* d_in, const int* in_sizes, int n_in,
                              void* d_out, int out_size) {
    const float* x  = (const float*)d_in[0];
    const int*   ei = (const int*)d_in[1];      // int32 words of edge_index (either dtype)
    const float* W1 = (const float*)d_in[2];
    const float* b1 = (const float*)d_in[3];
    const float* W2 = (const float*)d_in[4];
    const float* b2 = (const float*)d_in[5];
    float*       out = (float*)d_out;

    void *hw_p, *agg1_p, *h2w_p;
    cudaGetSymbolAddress(&hw_p,   g_hw);
    cudaGetSymbolAddress(&agg1_p, g_agg1);
    cudaGetSymbolAddress(&h2w_p,  g_h2w);

    constexpr int TPB = 256;
    const int nb_nodes = (N_NODES + TPB - 1) / TPB;
    const int nb_edges = (N_EDGES + TPB - 1) / TPB;

    detect_kernel<<<1, 128>>>(ei);
    zero_deg_kernel<<<nb_nodes, TPB>>>();
    deg_kernel<<<nb_edges, TPB>>>(ei);
    dinv_kernel<<<nb_nodes, TPB>>>();
    scan_kernel<<<1, 1024>>>();
    fill_kernel<<<nb_edges, TPB>>>();

    // ---- layer 1: X@W1 then aggregate (+bias,+self) ----
    constexpr int SMEM1 = (64 * (IN_CH + 4) + IN_CH * HIDDEN) * sizeof(float); // 66560
    cudaFuncSetAttribute(gemm_kernel<IN_CH, HIDDEN, false>,
                         cudaFuncAttributeMaxDynamicSharedMemorySize, SMEM1);
    gemm_kernel<IN_CH, HIDDEN, false>
        <<<(N_NODES + 63) / 64, 16 * (HIDDEN / 4), SMEM1>>>(x, W1, (float*)hw_p, N_NODES);

    const int nb_warps = (N_NODES * 32 + TPB - 1) / TPB;  // 1 warp per node
    aggregate_kernel<HIDDEN><<<nb_warps, TPB>>>((const float*)hw_p, b1, (float*)agg1_p);

    // ---- layer 2: relu fused into GEMM A-load ----
    constexpr int SMEM2 = (64 * (HIDDEN + 4) + HIDDEN * NCLS) * sizeof(float); // 27648
    cudaFuncSetAttribute(gemm_kernel<HIDDEN, NCLS, true>,
                         cudaFuncAttributeMaxDynamicSharedMemorySize, SMEM2);
    gemm_kernel<HIDDEN, NCLS, true>
        <<<(N_NODES + 63) / 64, 16 * (NCLS / 4), SMEM2>>>((const float*)agg1_p, W2,
                                                          (float*)h2w_p, N_NODES);

    aggregate_kernel<NCLS><<<nb_warps, TPB>>>((const float*)h2w_p, b2, out);
}

// round 4
// speedup vs baseline: 1.3589x; 1.3589x over previous
#include <cuda_runtime.h>
#include <cstdint>

#define N_NODES 100000
#define N_EDGES 1600000
#define IN_CH   128
#define HIDDEN  64
#define NCLS    40

// ---------------- scratch (device globals; no allocation allowed) ----------
__device__ int   g_is64;
__device__ int   g_deg[N_NODES];
__device__ int   g_off[N_NODES + 1];
__device__ int   g_cur[N_NODES];
__device__ float g_dinv[N_NODES];
__device__ int   g_bsum[128];
__device__ int   g_boff[128];
__device__ int2  g_adj[N_EDGES];                     // (src, norm-as-bits), grouped by dst
__device__ float g_hw  [(size_t)N_NODES * HIDDEN];   // X @ W1
__device__ float g_agg1[(size_t)N_NODES * HIDDEN];   // layer1 aggregated (pre-relu)
__device__ float g_h2w [(size_t)N_NODES * NCLS];     // relu(agg1) @ W2

// ---------------- packed f32x2 helpers --------------------------------------
__device__ __forceinline__ unsigned long long ffma2(unsigned long long a,
                                                    unsigned long long b,
                                                    unsigned long long c) {
    unsigned long long d;
    asm("fma.rn.f32x2 %0, %1, %2, %3;" : "=l"(d) : "l"(a), "l"(b), "l"(c));
    return d;
}
__device__ __forceinline__ unsigned long long pack2(float a) {
    unsigned long long d;
    asm("mov.b64 %0, {%1, %1};" : "=l"(d) : "f"(a));
    return d;
}

// ---------------- prep: zero degrees + detect index dtype -------------------
// int64 indices (<2^31) have zero high words at every odd int32 position.
__global__ void prep_kernel(const int* __restrict__ w) {
    int i = blockIdx.x * blockDim.x + threadIdx.x;
    if (i < N_NODES) g_deg[i] = 0;
    if (blockIdx.x == 0) {
        __shared__ int acc;
        if (threadIdx.x == 0) acc = 0;
        __syncthreads();
        int v = 0;
        for (int j = threadIdx.x; j < 4096; j += blockDim.x) v |= w[2 * j + 1];
        atomicOr(&acc, v);
        __syncthreads();
        if (threadIdx.x == 0) g_is64 = (acc == 0) ? 1 : 0;
    }
}

__global__ void deg_kernel(const int* __restrict__ w) {
    int e = blockIdx.x * blockDim.x + threadIdx.x;
    if (e >= N_EDGES) return;
    int d = g_is64 ? w[2 * (N_EDGES + e)] : w[N_EDGES + e];
    if ((unsigned)d >= N_NODES) d = 0;
    atomicAdd(&g_deg[d], 1);
}

// ---------------- 3-phase exclusive scan of g_deg ---------------------------
#define SCAN_NB  128
#define SCAN_TPB 256
#define SCAN_PER 4        // 128*256*4 = 131072 >= N_NODES

__global__ void scanA_kernel() {
    __shared__ int red[SCAN_TPB];
    int base = (blockIdx.x * SCAN_TPB + threadIdx.x) * SCAN_PER;
    int s = 0;
#pragma unroll
    for (int j = 0; j < SCAN_PER; j++) {
        int i = base + j;
        if (i < N_NODES) s += g_deg[i];
    }
    red[threadIdx.x] = s;
    __syncthreads();
    for (int o = SCAN_TPB / 2; o > 0; o >>= 1) {
        if (threadIdx.x < o) red[threadIdx.x] += red[threadIdx.x + o];
        __syncthreads();
    }
    if (threadIdx.x == 0) g_bsum[blockIdx.x] = red[0];
}

__global__ void scanB_kernel() {   // 1 block, SCAN_NB threads
    __shared__ int p[SCAN_NB];
    int t = threadIdx.x;
    p[t] = g_bsum[t];
    __syncthreads();
    for (int o = 1; o < SCAN_NB; o <<= 1) {
        int v = (t >= o) ? p[t - o] : 0;
        __syncthreads();
        p[t] += v;
        __syncthreads();
    }
    g_boff[t] = (t > 0) ? p[t - 1] : 0;
    if (t == SCAN_NB - 1) g_off[N_NODES] = p[t];
}

__global__ void scanC_kernel() {   // writes g_off, g_cur, g_dinv
    __shared__ int p[SCAN_TPB];
    int t = threadIdx.x;
    int base = (blockIdx.x * SCAN_TPB + t) * SCAN_PER;
    int loc[SCAN_PER];
    int s = 0;
#pragma unroll
    for (int j = 0; j < SCAN_PER; j++) {
        int i = base + j;
        int d = (i < N_NODES) ? g_deg[i] : 0;
        loc[j] = s;
        s += d;
    }
    p[t] = s;
    __syncthreads();
    for (int o = 1; o < SCAN_TPB; o <<= 1) {
        int v = (t >= o) ? p[t - o] : 0;
        __syncthreads();
        p[t] += v;
        __syncthreads();
    }
    int pre = g_boff[blockIdx.x] + ((t > 0) ? p[t - 1] : 0);
#pragma unroll
    for (int j = 0; j < SCAN_PER; j++) {
        int i = base + j;
        if (i < N_NODES) {
            int o = pre + loc[j];
            g_off[i] = o;
            g_cur[i] = o;
            g_dinv[i] = rsqrtf((float)(g_deg[i] + 1));  // +1 self loop
        }
    }
}

// counting-sort edges by dst into g_adj (re-decodes ei; norm precomputed)
__global__ void fill_kernel(const int* __restrict__ w) {
    int e = blockIdx.x * blockDim.x + threadIdx.x;
    if (e >= N_EDGES) return;
    int s, d;
    if (g_is64) { s = w[2 * e]; d = w[2 * (N_EDGES + e)]; }
    else        { s = w[e];     d = w[N_EDGES + e]; }
    if ((unsigned)s >= N_NODES) s = 0;
    if ((unsigned)d >= N_NODES) d = 0;
    int pos = atomicAdd(&g_cur[d], 1);
    g_adj[pos] = make_int2(s, __float_as_int(g_dinv[s] * g_dinv[d]));
}

// ---------------- GEMM: C[M,NDIM] = (relu?)A[M,KDIM] * W[KDIM,NDIM] --------
// ROWS rows/block, 4x8 micro-tile with packed fma.rn.f32x2 (2 cols/reg).
template<int KDIM, int NDIM, int ROWS, bool RELU>
__global__ void gemm_kernel(const float* __restrict__ A,
                            const float* __restrict__ W,
                            float* __restrict__ C, int M) {
    constexpr int TX    = NDIM / 8;     // 8 cols per thread
    constexpr int TY    = ROWS / 4;     // 4 rows per thread
    constexpr int NT    = TX * TY;
    constexpr int PITCH = KDIM + 4;
    extern __shared__ float smem[];
    float* sA = smem;                   // [ROWS][PITCH]
    float* sW = smem + ROWS * PITCH;    // [KDIM][NDIM]

    const int tid     = threadIdx.x;
    const int rowbase = blockIdx.x * ROWS;

    for (int v = tid; v < KDIM * NDIM / 4; v += NT)
        ((float4*)sW)[v] = ((const float4*)W)[v];

    constexpr int KC4 = KDIM / 4;
    for (int v = tid; v < ROWS * KC4; v += NT) {
        int r  = v / KC4;
        int kc = (v - r * KC4) * 4;
        int row = rowbase + r;
        float4 a = make_float4(0.f, 0.f, 0.f, 0.f);
        if (row < M) a = *(const float4*)(A + (size_t)row * KDIM + kc);
        if (RELU) {
            a.x = fmaxf(a.x, 0.f); a.y = fmaxf(a.y, 0.f);
            a.z = fmaxf(a.z, 0.f); a.w = fmaxf(a.w, 0.f);
        }
        *(float4*)(sA + r * PITCH + kc) = a;
    }
    __syncthreads();

    const int ty = tid / TX, tx = tid - (tid / TX) * TX;
    unsigned long long acc[4][4];       // [row][col-pair]
#pragma unroll
    for (int i = 0; i < 4; i++)
#pragma unroll
        for (int j = 0; j < 4; j++) acc[i][j] = 0ull;

#pragma unroll 4
    for (int k = 0; k < KDIM; k++) {
        ulonglong2 b01 = *(const ulonglong2*)(sW + k * NDIM + 8 * tx);
        ulonglong2 b23 = *(const ulonglong2*)(sW + k * NDIM + 8 * tx + 4);
#pragma unroll
        for (int i = 0; i < 4; i++) {
            unsigned long long pa = pack2(sA[(4 * ty + i) * PITCH + k]);
            acc[i][0] = ffma2(pa, b01.x, acc[i][0]);
            acc[i][1] = ffma2(pa, b01.y, acc[i][1]);
            acc[i][2] = ffma2(pa, b23.x, acc[i][2]);
            acc[i][3] = ffma2(pa, b23.y, acc[i][3]);
        }
    }

#pragma unroll
    for (int i = 0; i < 4; i++) {
        int row = rowbase + 4 * ty + i;
        if (row < M) {
            ulonglong2* p = (ulonglong2*)(C + (size_t)row * NDIM + 8 * tx);
            p[0] = make_ulonglong2(acc[i][0], acc[i][1]);
            p[1] = make_ulonglong2(acc[i][2], acc[i][3]);
        }
    }
}

// ---------------- CSR aggregation -------------------------------------------
// out[i] = bias + dinv_i^2*feat[i] + sum_j norm_ij*feat[src_j]
// one warp per node; lane groups of V4 lanes, each lane owns one float4 chunk,
// EP edges processed per iteration; cross-group shfl reduce at the end.
template<int CH>
__global__ void aggregate_kernel(const float* __restrict__ feat,
                                 const float* __restrict__ bias,
                                 float* __restrict__ out) {
    constexpr int V4 = CH / 4;       // 16 (CH=64) or 10 (CH=40)
    constexpr int EP = 32 / V4;      // 2 or 3
    int node = (blockIdx.x * blockDim.x + threadIdx.x) >> 5;
    if (node >= N_NODES) return;
    int lane = threadIdx.x & 31;
    int eg = lane / V4;              // edge group
    int c  = lane - eg * V4;         // float4 index within row
    bool act = eg < EP;              // lanes 30,31 idle when V4=10

    const int beg = g_off[node];
    const int end = g_off[node + 1];

    float4 acc = make_float4(0.f, 0.f, 0.f, 0.f);
    if (eg == 0) {                   // self-loop + bias only in group 0
        float dv = g_dinv[node];
        float s  = dv * dv;
        float4 f  = ((const float4*)(feat + (size_t)node * CH))[c];
        float4 bb = ((const float4*)bias)[c];
        acc.x = fmaf(s, f.x, bb.x);
        acc.y = fmaf(s, f.y, bb.y);
        acc.z = fmaf(s, f.z, bb.z);
        acc.w = fmaf(s, f.w, bb.w);
    }

    for (int k = beg; k < end; k += EP) {
        int e = k + eg;
        if (act && e < end) {
            int2 p = g_adj[e];
            float nrm = __int_as_float(p.y);
            float4 v = ((const float4*)(feat + (size_t)p.x * CH))[c];
            acc.x = fmaf(nrm, v.x, acc.x);
            acc.y = fmaf(nrm, v.y, acc.y);
            acc.z = fmaf(nrm, v.z, acc.z);
            acc.w = fmaf(nrm, v.w, acc.w);
        }
    }

    // reduce groups 1..EP-1 into group 0 (both shfls read pre-update values)
    const unsigned m = 0xffffffffu;
    float x1 = __shfl_down_sync(m, acc.x, V4);
    float y1 = __shfl_down_sync(m, acc.y, V4);
    float z1 = __shfl_down_sync(m, acc.z, V4);
    float w1 = __shfl_down_sync(m, acc.w, V4);
    if (EP > 2) {
        float x2 = __shfl_down_sync(m, acc.x, 2 * V4);
        float y2 = __shfl_down_sync(m, acc.y, 2 * V4);
        float z2 = __shfl_down_sync(m, acc.z, 2 * V4);
        float w2 = __shfl_down_sync(m, acc.w, 2 * V4);
        x1 += x2; y1 += y2; z1 += z2; w1 += w2;
    }
    acc.x += x1; acc.y += y1; acc.z += z1; acc.w += w1;

    if (eg == 0)
        ((float4*)(out + (size_t)node * CH))[c] = acc;
}

// ---------------- launch ----------------------------------------------------
extern "C" void kernel_launch(void* const* d_in, const int* in_sizes, int n_in,
                              void* d_out, int out_size) {
    const float* x  = (const float*)d_in[0];
    const int*   ei = (const int*)d_in[1];      // int32 words of edge_index (either dtype)
    const float* W1 = (const float*)d_in[2];
    const float* b1 = (const float*)d_in[3];
    const float* W2 = (const float*)d_in[4];
    const float* b2 = (const float*)d_in[5];
    float*       out = (float*)d_out;

    void *hw_p, *agg1_p, *h2w_p;
    cudaGetSymbolAddress(&hw_p,   g_hw);
    cudaGetSymbolAddress(&agg1_p, g_agg1);
    cudaGetSymbolAddress(&h2w_p,  g_h2w);

    constexpr int TPB = 256;
    const int nb_nodes = (N_NODES + TPB - 1) / TPB;
    const int nb_edges = (N_EDGES + TPB - 1) / TPB;

    prep_kernel<<<nb_nodes, TPB>>>(ei);
    deg_kernel<<<nb_edges, TPB>>>(ei);
    scanA_kernel<<<SCAN_NB, SCAN_TPB>>>();
    scanB_kernel<<<1, SCAN_NB>>>();
    scanC_kernel<<<SCAN_NB, SCAN_TPB>>>();
    fill_kernel<<<nb_edges, TPB>>>(ei);

    // ---- layer 1: X@W1 then aggregate (+bias,+self) ----
    constexpr int SMEM1 = (64 * (IN_CH + 4) + IN_CH * HIDDEN) * sizeof(float); // 66560
    cudaFuncSetAttribute(gemm_kernel<IN_CH, HIDDEN, 64, false>,
                         cudaFuncAttributeMaxDynamicSharedMemorySize, SMEM1);
    gemm_kernel<IN_CH, HIDDEN, 64, false>
        <<<(N_NODES + 63) / 64, (HIDDEN / 8) * 16, SMEM1>>>(x, W1, (float*)hw_p, N_NODES);

    const int nb_warps = (N_NODES * 32 + TPB - 1) / TPB;  // 1 warp per node
    aggregate_kernel<HIDDEN><<<nb_warps, TPB>>>((const float*)hw_p, b1, (float*)agg1_p);

    // ---- layer 2: relu fused into GEMM A-load ----
    constexpr int SMEM2 = (128 * (HIDDEN + 4) + HIDDEN * NCLS) * sizeof(float); // 45056
    cudaFuncSetAttribute(gemm_kernel<HIDDEN, NCLS, 128, true>,
                         cudaFuncAttributeMaxDynamicSharedMemorySize, SMEM2);
    gemm_kernel<HIDDEN, NCLS, 128, true>
        <<<(N_NODES + 127) / 128, (NCLS / 8) * 32, SMEM2>>>((const float*)agg1_p, W2,
                                                            (float*)h2w_p, N_NODES);

    aggregate_kernel<NCLS><<<nb_warps, TPB>>>((const float*)h2w_p, b2, out);
}